// round 17
// baseline (speedup 1.0000x reference)
#include <cuda_runtime.h>
#include <cuda_bf16.h>
#include <stdint.h>
#include <math.h>

// ---------------- problem constants ----------------
#define NPTS   100000
#define DIN    128
#define D2     64
#define DOUT   256
#define KPTS   15
#define SIGMA  0.04f
#define NEG    0.1f
#define EPSBN  1e-5f
#define CAP    48

// ---------------- scratch (device globals; no runtime alloc) ----------------
__device__ float  g_t  [(size_t)NPTS * D2];      // fp32 GEMM out (t, then y)
__device__ float  g_u2 [(size_t)NPTS * DOUT];
__device__ float  g_usc[(size_t)NPTS * DOUT];
__device__ __align__(16) __nv_bfloat16 g_Sb [(size_t)NPTS * 2 * KPTS * D2];  // S split
__device__ __align__(16) __nv_bfloat16 g_w1b [D2   * 2 * DIN];
__device__ __align__(16) __nv_bfloat16 g_wkpb[D2   * 2 * (KPTS*D2)];
__device__ __align__(16) __nv_bfloat16 g_w2b [DOUT * 2 * D2];
__device__ __align__(16) __nv_bfloat16 g_wscb[DOUT * 2 * DIN];
__device__ int    g_cnt[NPTS];
__device__ int    g_nbr[(size_t)NPTS * CAP];
__device__ __align__(16) float g_inf[(size_t)NPTS * CAP * 16];   // per-slot influence rows (307 MB)
__device__ double g_stats[1280];
__device__ float2 g_bnp[640];

// ---------------- small kernels ----------------
__global__ void zero_kernel() {
    int i = blockIdx.x * blockDim.x + threadIdx.x;
    if (i < NPTS) g_cnt[i] = 0;
    if (i < 1280) g_stats[i] = 0.0;
}

// scatter v2: half-warp per edge; computes influences, drops dead edges,
// writes fp32 influence row + neighbor id.
__global__ __launch_bounds__(256) void scatter_kernel(
    const int* __restrict__ e_ref, const int* __restrict__ e_qry,
    const float* __restrict__ pos, const float* __restrict__ kp, int E)
{
    __shared__ float skp[45];
    int tid = threadIdx.x;
    int lane = tid & 31;
    int warp = tid >> 5;
    if (tid < 45) skp[tid] = kp[tid];
    __syncthreads();

    int half = lane >> 4;
    int k = lane & 15;
    long e = (long)blockIdx.x * 16 + warp * 2 + half;
    bool ev = (e < E);

    int r = 0, q = 0;
    float infl = 0.f;
    if (ev) {
        r = __ldg(&e_ref[e]);
        q = __ldg(&e_qry[e]);
        float4 pr = __ldg((const float4*)pos + r);
        float4 pq = __ldg((const float4*)pos + q);
        if (k < KPTS) {
            float dx = (pr.y - pq.y) - skp[k * 3 + 0];
            float dy = (pr.z - pq.z) - skp[k * 3 + 1];
            float dz = (pr.w - pq.w) - skp[k * 3 + 2];
            float d2 = dx * dx + dy * dy + dz * dz;
            if (d2 < SIGMA * SIGMA)
                infl = 1.f - sqrtf(d2) * (1.f / SIGMA);
        }
    }
    unsigned m = __ballot_sync(0xffffffffu, infl > 0.f);
    unsigned mh = (m >> (half << 4)) & 0xFFFFu;

    int slot = -1;
    if (k == 0 && mh) slot = atomicAdd(&g_cnt[q], 1);
    slot = __shfl_sync(0xffffffffu, slot, half << 4);

    if (mh && slot >= 0 && slot < CAP) {
        g_inf[((size_t)q * CAP + slot) * 16 + k] = infl;   // k=15 lane writes 0 pad
        if (k == 0) g_nbr[(size_t)q * CAP + slot] = r;
    }
}

__device__ __forceinline__ void bsplit(float v, __nv_bfloat16& h, __nv_bfloat16& l) {
    h = __float2bfloat16(v);
    l = __float2bfloat16(v - __bfloat162float(h));
}

__device__ __forceinline__ void wsplit_one(const float* W, __nv_bfloat16* out,
                                           int i, int K, int N) {
    int k = i / N, n = i % N;
    __nv_bfloat16 h, l;
    bsplit(W[i], h, l);
    out[(size_t)n * 2 * K + k] = h;
    out[(size_t)n * 2 * K + K + k] = l;
}

#define WSPLIT_TOTAL 118784
__global__ void wsplit_all(const float* __restrict__ W1, const float* __restrict__ Wkp,
                           const float* __restrict__ W2, const float* __restrict__ Wsc) {
    int i = blockIdx.x * blockDim.x + threadIdx.x;
    if (i >= WSPLIT_TOTAL) return;
    if (i < 8192) {
        wsplit_one(W1, g_w1b, i, DIN, D2);
    } else if (i < 69632) {
        wsplit_one(Wkp, g_wkpb, i - 8192, KPTS * D2, D2);
    } else if (i < 86016) {
        wsplit_one(W2, g_w2b, i - 69632, D2, DOUT);
    } else {
        wsplit_one(Wsc, g_wscb, i - 86016, DIN, DOUT);
    }
}

__global__ void bn_prep(int statOff, int C, const float* __restrict__ g,
                        const float* __restrict__ b, int prepOff, int M) {
    int i = threadIdx.x;
    if (i >= C) return;
    double m = g_stats[statOff + i] / (double)M;
    double v = g_stats[statOff + C + i] / (double)M - m * m;
    float rstd = rsqrtf((float)v + EPSBN);
    float scale = g[i] * rstd;
    float shift = b[i] - (float)m * scale;
    g_bnp[prepOff + i] = make_float2(scale, shift);
}

__global__ void bn_prep2(const float* __restrict__ g2, const float* __restrict__ b2,
                         const float* __restrict__ gsc, const float* __restrict__ bsc,
                         int M) {
    int tid = threadIdx.x;
    int i = tid & 255;
    int which = tid >> 8;
    int statOff = which ? 768 : 256;
    int prepOff = which ? 384 : 128;
    const float* g = which ? gsc : g2;
    const float* b = which ? bsc : b2;
    double m = g_stats[statOff + i] / (double)M;
    double v = g_stats[statOff + DOUT + i] / (double)M - m * m;
    float rstd = rsqrtf((float)v + EPSBN);
    float scale = g[i] * rstd;
    float shift = b[i] - (float)m * scale;
    g_bnp[prepOff + i] = make_float2(scale, shift);
}

// ---------------- S build v2: pure-FMA inner loop (influences precomputed) ----------------
__global__ __launch_bounds__(256) void sbuild_kernel() {
    int tid = threadIdx.x;
    int lane = tid & 31;
    int warp = tid >> 5;
    int q = blockIdx.x * 8 + warp;
    if (q >= NPTS) return;

    float2 p0 = __ldg(&g_bnp[2 * lane]);
    float2 p1 = __ldg(&g_bnp[2 * lane + 1]);

    float a0[KPTS], a1[KPTS];
#pragma unroll
    for (int k = 0; k < KPTS; ++k) { a0[k] = 0.f; a1[k] = 0.f; }

    int cnt = g_cnt[q];
    if (cnt > CAP) cnt = CAP;
    const int* nb = g_nbr + (size_t)q * CAP;
    const float4* ib = (const float4*)(g_inf + (size_t)q * CAP * 16);

    for (int j = 0; j < cnt; ++j) {
        int r = __ldg(&nb[j]);
        float4 i0 = __ldg(ib + j * 4 + 0);
        float4 i1 = __ldg(ib + j * 4 + 1);
        float4 i2 = __ldg(ib + j * 4 + 2);
        float4 i3 = __ldg(ib + j * 4 + 3);
        float2 hv = __ldg((const float2*)g_t + (size_t)r * 32 + lane);
        float h0 = fmaf(hv.x, p0.x, p0.y);
        h0 = (h0 >= 0.f) ? h0 : NEG * h0;
        float h1 = fmaf(hv.y, p1.x, p1.y);
        h1 = (h1 >= 0.f) ? h1 : NEG * h1;

        a0[0]  = fmaf(i0.x, h0, a0[0]);  a1[0]  = fmaf(i0.x, h1, a1[0]);
        a0[1]  = fmaf(i0.y, h0, a0[1]);  a1[1]  = fmaf(i0.y, h1, a1[1]);
        a0[2]  = fmaf(i0.z, h0, a0[2]);  a1[2]  = fmaf(i0.z, h1, a1[2]);
        a0[3]  = fmaf(i0.w, h0, a0[3]);  a1[3]  = fmaf(i0.w, h1, a1[3]);
        a0[4]  = fmaf(i1.x, h0, a0[4]);  a1[4]  = fmaf(i1.x, h1, a1[4]);
        a0[5]  = fmaf(i1.y, h0, a0[5]);  a1[5]  = fmaf(i1.y, h1, a1[5]);
        a0[6]  = fmaf(i1.z, h0, a0[6]);  a1[6]  = fmaf(i1.z, h1, a1[6]);
        a0[7]  = fmaf(i1.w, h0, a0[7]);  a1[7]  = fmaf(i1.w, h1, a1[7]);
        a0[8]  = fmaf(i2.x, h0, a0[8]);  a1[8]  = fmaf(i2.x, h1, a1[8]);
        a0[9]  = fmaf(i2.y, h0, a0[9]);  a1[9]  = fmaf(i2.y, h1, a1[9]);
        a0[10] = fmaf(i2.z, h0, a0[10]); a1[10] = fmaf(i2.z, h1, a1[10]);
        a0[11] = fmaf(i2.w, h0, a0[11]); a1[11] = fmaf(i2.w, h1, a1[11]);
        a0[12] = fmaf(i3.x, h0, a0[12]); a1[12] = fmaf(i3.x, h1, a1[12]);
        a0[13] = fmaf(i3.y, h0, a0[13]); a1[13] = fmaf(i3.y, h1, a1[13]);
        a0[14] = fmaf(i3.z, h0, a0[14]); a1[14] = fmaf(i3.z, h1, a1[14]);
    }

    __nv_bfloat162* Sout = (__nv_bfloat162*)(g_Sb + (size_t)q * 1920);
#pragma unroll
    for (int k = 0; k < KPTS; ++k) {
        __nv_bfloat16 h0, l0, h1, l1;
        bsplit(a0[k], h0, l0);
        bsplit(a1[k], h1, l1);
        __nv_bfloat162 hh; hh.x = h0; hh.y = h1;
        __nv_bfloat162 ll; ll.x = l0; ll.y = l1;
        Sout[k * 32 + lane] = hh;
        Sout[480 + k * 32 + lane] = ll;
    }
}

// ---------------- MMA / LDSM / cp.async helpers ----------------
__device__ __forceinline__ void mma16816(float* c, const uint32_t* a, const uint32_t* b) {
    asm volatile(
        "mma.sync.aligned.m16n8k16.row.col.f32.bf16.bf16.f32 "
        "{%0,%1,%2,%3}, {%4,%5,%6,%7}, {%8,%9}, {%0,%1,%2,%3};"
        : "+f"(c[0]), "+f"(c[1]), "+f"(c[2]), "+f"(c[3])
        : "r"(a[0]), "r"(a[1]), "r"(a[2]), "r"(a[3]), "r"(b[0]), "r"(b[1]));
}

#define LDSM4(r, addr) \
    asm volatile("ldmatrix.sync.aligned.m8n8.x4.shared.b16 {%0,%1,%2,%3}, [%4];" \
        : "=r"((r)[0]), "=r"((r)[1]), "=r"((r)[2]), "=r"((r)[3]) : "r"(addr))

__device__ __forceinline__ void cp16(uint32_t dst, const void* src, int sz) {
    asm volatile("cp.async.cg.shared.global [%0], [%1], 16, %2;"
                 :: "r"(dst), "l"(src), "r"(sz));
}
#define CP_COMMIT() asm volatile("cp.async.commit_group;" ::: "memory")
#define CP_WAIT0()  asm volatile("cp.async.wait_group 0;" ::: "memory")

#define ROWP 40
#define A_SEC (128 * ROWP)
#define B_SEC (64 * ROWP)
#define STAGE_BYTES ((2 * A_SEC + 2 * B_SEC) * 2)     // 30720
#define GSMEM_BYTES (2 * STAGE_BYTES + 512)           // 61952 -> 3 CTAs/SM

struct LdsmOff {
    uint32_t a0, a1, b0, b1;
};
__device__ __forceinline__ LdsmOff ldsm_offsets(int wm, int wn, int lane) {
    LdsmOff o;
    int aRow = wm * 32 + (lane & 15);
    int aCol = ((lane >> 4) & 1) * 8;
    o.a0 = (uint32_t)((aRow * ROWP + aCol) * 2);
    o.a1 = (uint32_t)(((aRow + 16) * ROWP + aCol) * 2);
    int bRow = wn * 32 + (((lane >> 4) & 1) << 3) + (lane & 7);
    int bCol = ((lane >> 3) & 1) * 8;
    o.b0 = (uint32_t)((bRow * ROWP + bCol) * 2);
    o.b1 = (uint32_t)(((bRow + 16) * ROWP + bCol) * 2);
    return o;
}

__device__ __forceinline__ void mma_chunk(
    float acc[2][4][4], const LdsmOff& o, uint32_t stageBase)
{
    uint32_t uAh = stageBase;
    uint32_t uAl = stageBase + A_SEC * 2;
    uint32_t uBh = stageBase + 4 * A_SEC;
    uint32_t uBl = uBh + B_SEC * 2;
#pragma unroll
    for (int ks = 0; ks < 2; ++ks) {
        uint32_t cb = ks * 32;
        uint32_t ah[2][4], al[2][4], bh[2][4], bl[2][4];
        LDSM4(ah[0], uAh + o.a0 + cb);
        LDSM4(ah[1], uAh + o.a1 + cb);
        LDSM4(al[0], uAl + o.a0 + cb);
        LDSM4(al[1], uAl + o.a1 + cb);
        LDSM4(bh[0], uBh + o.b0 + cb);
        LDSM4(bh[1], uBh + o.b1 + cb);
        LDSM4(bl[0], uBl + o.b0 + cb);
        LDSM4(bl[1], uBl + o.b1 + cb);
#pragma unroll
        for (int mi = 0; mi < 2; ++mi)
#pragma unroll
            for (int ni = 0; ni < 4; ++ni) {
                const uint32_t* pbh = &bh[ni >> 1][(ni & 1) * 2];
                const uint32_t* pbl = &bl[ni >> 1][(ni & 1) * 2];
                mma16816(acc[mi][ni], ah[mi], pbh);
                mma16816(acc[mi][ni], ah[mi], pbl);
                mma16816(acc[mi][ni], al[mi], pbh);
            }
    }
}

// ---------------- unified pipelined GEMM (identical to round 16) ----------------
template <int AMODE>
__global__ __launch_bounds__(256, 3) void gemm_uni(
    const void* __restrict__ Aptr,
    const __nv_bfloat16* __restrict__ B,
    float* __restrict__ C,
    int M, int K, int Nc, int statOff, int prepOff)
{
    extern __shared__ char smem[];
    float* red = (float*)(smem + 2 * STAGE_BYTES);

    const int tid = threadIdx.x;
    const int lane = tid & 31;
    const int wid = tid >> 5;
    const int wm = wid & 3;
    const int wn = wid >> 2;
    const int g = lane >> 2;
    const int t = lane & 3;
    const int m0 = blockIdx.x * 128;
    const int n0 = blockIdx.y * 64;
    const int ldb = 2 * K;
    const int nch = K >> 5;

    const LdsmOff off = ldsm_offsets(wm, wn, lane);
    const uint32_t uS = (uint32_t)__cvta_generic_to_shared(smem);

    if (tid < 128) red[tid] = 0.f;

    auto stageA_cp = [&](int c, uint32_t base) {
        const __nv_bfloat16* A = (const __nv_bfloat16*)Aptr;
        int koh = c * 32;
#pragma unroll
        for (int i = 0; i < 2; ++i) {
            int idx = tid + 256 * i;
            int r = idx >> 2, cw = idx & 3;
            int gr = m0 + r;
            int sz = (gr < M) ? 16 : 0;
            int gra = (gr < M) ? gr : 0;
            const __nv_bfloat16* sh = A + (size_t)gra * ldb + koh + cw * 8;
            const __nv_bfloat16* sl = sh + K;
            uint32_t d = base + (uint32_t)(r * ROWP + cw * 8) * 2;
            cp16(d, sh, sz);
            cp16(d + A_SEC * 2, sl, sz);
        }
    };
    auto stageB_cp = [&](int c, uint32_t base) {
        int koh = c * 32;
        if (tid < 256) {
            int r = tid >> 2, cw = tid & 3;
            const __nv_bfloat16* sh = B + (size_t)(n0 + r) * ldb + koh + cw * 8;
            const __nv_bfloat16* sl = sh + K;
            uint32_t d = base + (uint32_t)(4 * A_SEC) + (uint32_t)(r * ROWP + cw * 8) * 2;
            cp16(d, sh, 16);
            cp16(d + B_SEC * 2, sl, 16);
        }
    };
    float4 av[4];
    auto loadA = [&](int c) {
        const float* A32 = (const float*)Aptr;
        int koh = c * 32;
#pragma unroll
        for (int i = 0; i < 4; ++i) {
            int idx = tid + 256 * i;
            int r = idx >> 3;
            int cc = (idx & 7) * 4;
            int gr = m0 + r;
            av[i] = (gr < M) ? __ldg((const float4*)(A32 + (size_t)gr * K + koh + cc))
                             : make_float4(0.f, 0.f, 0.f, 0.f);
        }
    };
    auto storeA = [&](int c, uint32_t baseOff) {
        __nv_bfloat16* sA = (__nv_bfloat16*)(smem + baseOff);
        int koh = c * 32;
#pragma unroll
        for (int i = 0; i < 4; ++i) {
            int idx = tid + 256 * i;
            int r = idx >> 3;
            int cc = (idx & 7) * 4;
            __nv_bfloat16 h[4], l[4];
#pragma unroll
            for (int j = 0; j < 4; ++j) {
                float u = (&av[i].x)[j];
                if (AMODE == 2) {
                    float2 p = __ldg(&g_bnp[prepOff + koh + cc + j]);
                    u = fmaf(u, p.x, p.y);
                    u = (u >= 0.f) ? u : NEG * u;
                }
                bsplit(u, h[j], l[j]);
            }
            __nv_bfloat162 h01, h23, l01, l23;
            h01.x = h[0]; h01.y = h[1]; h23.x = h[2]; h23.y = h[3];
            l01.x = l[0]; l01.y = l[1]; l23.x = l[2]; l23.y = l[3];
            uint2 hp, lp;
            hp.x = *(uint32_t*)&h01; hp.y = *(uint32_t*)&h23;
            lp.x = *(uint32_t*)&l01; lp.y = *(uint32_t*)&l23;
            *(uint2*)(sA + r * ROWP + cc) = hp;
            *(uint2*)(sA + A_SEC + r * ROWP + cc) = lp;
        }
    };

    float acc[2][4][4];
#pragma unroll
    for (int mi = 0; mi < 2; ++mi)
#pragma unroll
        for (int ni = 0; ni < 4; ++ni)
#pragma unroll
            for (int j = 0; j < 4; ++j) acc[mi][ni][j] = 0.f;

    if (AMODE == 0) {
        stageA_cp(0, uS);
    } else {
        loadA(0);
        storeA(0, 0);
    }
    stageB_cp(0, uS);
    CP_COMMIT();

    for (int c = 0; c < nch; ++c) {
        int p = c & 1;
        CP_WAIT0();
        __syncthreads();
        bool more = (c + 1 < nch);
        if (more) {
            uint32_t nbase = uS + (p ^ 1) * STAGE_BYTES;
            if (AMODE == 0) stageA_cp(c + 1, nbase);
            else            loadA(c + 1);
            stageB_cp(c + 1, nbase);
            CP_COMMIT();
        }
        mma_chunk(acc, off, uS + p * STAGE_BYTES);
        if (more && AMODE != 0)
            storeA(c + 1, (uint32_t)((p ^ 1) * STAGE_BYTES));
    }
    __syncthreads();

#pragma unroll
    for (int ni = 0; ni < 4; ++ni) {
        int colL = wn * 32 + ni * 8 + 2 * t;
        float s0 = 0.f, q0 = 0.f, s1 = 0.f, q1 = 0.f;
#pragma unroll
        for (int mi = 0; mi < 2; ++mi) {
            float* f = acc[mi][ni];
            int row = m0 + wm * 32 + mi * 16 + g;
            if (row < M) {
                C[(size_t)row * Nc + n0 + colL] = f[0];
                C[(size_t)row * Nc + n0 + colL + 1] = f[1];
                s0 += f[0]; q0 += f[0] * f[0];
                s1 += f[1]; q1 += f[1] * f[1];
            }
            if (row + 8 < M) {
                C[(size_t)(row + 8) * Nc + n0 + colL] = f[2];
                C[(size_t)(row + 8) * Nc + n0 + colL + 1] = f[3];
                s0 += f[2]; q0 += f[2] * f[2];
                s1 += f[3]; q1 += f[3] * f[3];
            }
        }
#pragma unroll
        for (int off2 = 4; off2 < 32; off2 <<= 1) {
            s0 += __shfl_xor_sync(0xffffffffu, s0, off2);
            q0 += __shfl_xor_sync(0xffffffffu, q0, off2);
            s1 += __shfl_xor_sync(0xffffffffu, s1, off2);
            q1 += __shfl_xor_sync(0xffffffffu, q1, off2);
        }
        if (g == 0) {
            atomicAdd(&red[colL], s0);
            atomicAdd(&red[64 + colL], q0);
            atomicAdd(&red[colL + 1], s1);
            atomicAdd(&red[64 + colL + 1], q1);
        }
    }
    __syncthreads();
    if (tid < 64) {
        atomicAdd(&g_stats[statOff + n0 + tid], (double)red[tid]);
        atomicAdd(&g_stats[statOff + Nc + n0 + tid], (double)red[64 + tid]);
    }
}

// ---------------- final: out = leaky(bn(u2)) + bn(usc), float4 ----------------
__global__ void final_kernel(float4* __restrict__ out, int n4) {
    int i = blockIdx.x * blockDim.x + threadIdx.x;
    if (i >= n4) return;
    int c4 = (i & 63) * 4;
    float4 a = __ldg((const float4*)g_u2 + i);
    float4 s = __ldg((const float4*)g_usc + i);
    float4 o;
#pragma unroll
    for (int j = 0; j < 4; ++j) {
        float2 p2 = __ldg(&g_bnp[128 + c4 + j]);
        float2 ps = __ldg(&g_bnp[384 + c4 + j]);
        float u = fmaf((&a.x)[j], p2.x, p2.y);
        u = (u >= 0.f) ? u : NEG * u;
        (&o.x)[j] = u + fmaf((&s.x)[j], ps.x, ps.y);
    }
    out[i] = o;
}

// ---------------- launch (multi-stream graph fork/join) ----------------
extern "C" void kernel_launch(void* const* d_in, const int* in_sizes, int n_in,
                              void* d_out, int out_size) {
    const float* pos    = (const float*)d_in[0];
    const float* x      = (const float*)d_in[1];
    const int*   e_ref  = (const int*)  d_in[2];
    const int*   e_qry  = (const int*)  d_in[3];
    const float* W1     = (const float*)d_in[4];
    const float* g1     = (const float*)d_in[5];
    const float* b1     = (const float*)d_in[6];
    const float* kp     = (const float*)d_in[7];
    const float* Wkp    = (const float*)d_in[8];
    const float* gkp    = (const float*)d_in[9];
    const float* bkp    = (const float*)d_in[10];
    const float* W2     = (const float*)d_in[11];
    const float* g2     = (const float*)d_in[12];
    const float* b2     = (const float*)d_in[13];
    const float* Wsc    = (const float*)d_in[14];
    const float* gsc    = (const float*)d_in[15];
    const float* bsc    = (const float*)d_in[16];
    float* out = (float*)d_out;

    const int M = NPTS;
    const int E = in_sizes[2];

    float *t_p, *u2_p, *usc_p;
    __nv_bfloat16 *Sb_p, *wkpb_p, *w1b_p, *w2b_p, *wscb_p;
    cudaGetSymbolAddress((void**)&t_p,    g_t);
    cudaGetSymbolAddress((void**)&u2_p,   g_u2);
    cudaGetSymbolAddress((void**)&usc_p,  g_usc);
    cudaGetSymbolAddress((void**)&Sb_p,   g_Sb);
    cudaGetSymbolAddress((void**)&w1b_p,  g_w1b);
    cudaGetSymbolAddress((void**)&wkpb_p, g_wkpb);
    cudaGetSymbolAddress((void**)&w2b_p,  g_w2b);
    cudaGetSymbolAddress((void**)&wscb_p, g_wscb);

    cudaFuncSetAttribute(gemm_uni<0>, cudaFuncAttributeMaxDynamicSharedMemorySize, GSMEM_BYTES);
    cudaFuncSetAttribute(gemm_uni<1>, cudaFuncAttributeMaxDynamicSharedMemorySize, GSMEM_BYTES);
    cudaFuncSetAttribute(gemm_uni<2>, cudaFuncAttributeMaxDynamicSharedMemorySize, GSMEM_BYTES);

    static cudaStream_t s2 = nullptr;
    static cudaEvent_t ev0 = nullptr, evW = nullptr, evS = nullptr, evU = nullptr;
    if (s2 == nullptr) {
        cudaStreamCreateWithFlags(&s2, cudaStreamNonBlocking);
        cudaEventCreateWithFlags(&ev0, cudaEventDisableTiming);
        cudaEventCreateWithFlags(&evW, cudaEventDisableTiming);
        cudaEventCreateWithFlags(&evS, cudaEventDisableTiming);
        cudaEventCreateWithFlags(&evU, cudaEventDisableTiming);
    }

    const int MB = (M + 127) / 128;
    int n4_256 = M * DOUT / 4;

    // ---- default stream: start of critical chain ----
    zero_kernel<<<(NPTS + 255) / 256, 256>>>();
    cudaEventRecord(ev0, 0);
    wsplit_all<<<(WSPLIT_TOTAL + 255) / 256, 256>>>(W1, Wkp, W2, Wsc);
    cudaEventRecord(evW, 0);

    // ---- side stream: influence-computing scatter, then usc GEMM ----
    cudaStreamWaitEvent(s2, ev0, 0);
    scatter_kernel<<<(E + 15) / 16, 256, 0, s2>>>(e_ref, e_qry, pos, kp, E);
    cudaEventRecord(evS, s2);
    cudaStreamWaitEvent(s2, evW, 0);
    gemm_uni<1><<<dim3(MB, 4), 256, GSMEM_BYTES, s2>>>(x, wscb_p, usc_p, M, DIN, DOUT, 768, 0);
    cudaEventRecord(evU, s2);

    // ---- default stream: critical chain continues ----
    gemm_uni<1><<<dim3(MB, 1), 256, GSMEM_BYTES>>>(x, w1b_p, t_p, M, DIN, D2, 0, 0);
    bn_prep<<<1, 64>>>(0, D2, g1, b1, 0, M);
    cudaStreamWaitEvent(0, evS, 0);
    sbuild_kernel<<<(M + 7) / 8, 256>>>();
    gemm_uni<0><<<dim3(MB, 1), 256, GSMEM_BYTES>>>(Sb_p, wkpb_p, t_p, M, KPTS * D2, D2, 128, 0);
    bn_prep<<<1, 64>>>(128, D2, gkp, bkp, 64, M);
    gemm_uni<2><<<dim3(MB, 4), 256, GSMEM_BYTES>>>(t_p, w2b_p, u2_p, M, D2, DOUT, 256, 64);
    cudaStreamWaitEvent(0, evU, 0);
    bn_prep2<<<1, 512>>>(g2, b2, gsc, bsc, M);
    final_kernel<<<(n4_256 + 255) / 256, 256>>>((float4*)out, n4_256);
}